// round 17
// baseline (speedup 1.0000x reference)
#include <cuda_runtime.h>
#include <cuda_fp16.h>
#include <cstdint>

#define LATENT 16
#define HID 512
#define DD 64
#define NB 128
#define NG 128
#define OUTSZ 12610
#define OUTSZ_PAD 12612

// Scratch (device globals — no allocation allowed)
__device__ float g_h1p[4 * NB * HID];  // split-K partials of h1
__device__ __half g_h1h[NB * HID];     // fp16-hi split of h1, [m][k]
__device__ __half g_h1l[NB * HID];     // fp16-lo split of h1, [m][k]
__device__ float g_wb[NB * OUTSZ_PAD]; // PRE-PERMUTED into decoder layout

typedef unsigned long long u64;

__device__ __forceinline__ u64 pack2(float lo, float hi) {
    u64 r; asm("mov.b64 %0, {%1, %2};" : "=l"(r) : "f"(lo), "f"(hi)); return r;
}
__device__ __forceinline__ void fma2(u64& d, u64 a, u64 b) {
    asm("fma.rn.f32x2 %0, %1, %2, %0;" : "+l"(d) : "l"(a), "l"(b));
}

__device__ __forceinline__ float leaky(float x) { return x > 0.0f ? x : 0.01f * x; }

// fast sin: 2-step Cody-Waite range reduction + MUFU sin (args stay < ~40)
__device__ __forceinline__ float fsin(float x) {
    float k = rintf(x * 0.15915494309189535f);
    x = fmaf(k, -6.28125f, x);
    x = fmaf(k, -1.9353071795864769e-3f, x);
    return __sinf(x);
}

// pack two fp32 into one u32 of 2 fp16 (lo half = first arg)
__device__ __forceinline__ uint32_t packh2(float vlo, float vhi) {
    uint32_t d;
    asm("cvt.rn.f16x2.f32 %0, %1, %2;" : "=r"(d) : "f"(vhi), "f"(vlo));
    return d;
}

__device__ __forceinline__ uint32_t smem_u32(const void* p) {
    uint32_t a;
    asm("{ .reg .u64 t; cvta.to.shared.u64 t, %1; cvt.u32.u64 %0, t; }"
        : "=r"(a) : "l"(p));
    return a;
}

// PDL: wait until the producer kernel's writes are visible
__device__ __forceinline__ void gdc_wait() {
    asm volatile("griddepcontrol.wait;" ::: "memory");
}

// ldmatrix: 4 / 2 8x8 b16 matrices per warp-collective instruction
__device__ __forceinline__ void ldsm4(uint32_t* r, uint32_t a) {
    asm volatile("ldmatrix.sync.aligned.m8n8.x4.shared.b16 {%0,%1,%2,%3}, [%4];"
                 : "=r"(r[0]), "=r"(r[1]), "=r"(r[2]), "=r"(r[3]) : "r"(a));
}
__device__ __forceinline__ void ldsm2(uint32_t* r, uint32_t a) {
    asm volatile("ldmatrix.sync.aligned.m8n8.x2.shared.b16 {%0,%1}, [%2];"
                 : "=r"(r[0]), "=r"(r[1]) : "r"(a));
}

// fp16 mma m16n8k16 (fragment mappings validated rounds 10-16)
__device__ __forceinline__ void mma_f16(float4& c, const uint32_t a[4],
                                        const uint32_t b[2]) {
    asm volatile(
        "mma.sync.aligned.m16n8k16.row.col.f32.f16.f16.f32 "
        "{%0,%1,%2,%3}, {%4,%5,%6,%7}, {%8,%9}, {%0,%1,%2,%3};"
        : "+f"(c.x), "+f"(c.y), "+f"(c.z), "+f"(c.w)
        : "r"(a[0]), "r"(a[1]), "r"(a[2]), "r"(a[3]), "r"(b[0]), "r"(b[1]));
}

// Decoder layout (floats): W1[0,4096) W2[4096,8192) W3[8192,12288) W0[12288,12352)
// b1[12352,12416) b2[12416,12480) b3[12480,12544) W4[12544,12608) b0[12608] b4[12609]
#define OFF_W0 12288
#define OFF_B  12352
#define OFF_W4 12544

__device__ __forceinline__ int perm_wb(int n) {
    if (n < 4161)  return (n < 64) ? 12288 + n : (n == 64 ? 12608 : n - 65);
    if (n < 8321)  return (n < 4225) ? 12352 + (n - 4161) : 4096 + (n - 4225);
    if (n < 12481) return (n < 8385) ? 12416 + (n - 8321) : 8192 + (n - 8385);
    if (n < 12545) return 12480 + (n - 12481);
    return (n < 12609) ? 12544 + (n - 12545) : 12609;
}

// ---------------------------------------------------------------------------
// h1 split-K GEMM with lean fused h0. Grid (8,8,4) = 256 CTAs x 128 thr.
// ---------------------------------------------------------------------------
#define H1_AD_STR 17

__global__ void __launch_bounds__(128)
k_h1split(const float* __restrict__ z, const float* __restrict__ hw0,
          const float* __restrict__ hb0, const float* __restrict__ hw1,
          float* __restrict__ partial) {
    __shared__ __align__(16) u64 Ad[128 * H1_AD_STR];
    __shared__ __align__(16) float Bs[2][16][64];
    __shared__ float zs[256];

    int tid = threadIdx.x;
    int tx = tid & 15, ty = tid >> 4;
    int n0 = blockIdx.x * 64;
    int m0 = blockIdx.y * 16;
    int kbase = blockIdx.z * 128;

    for (int e = tid; e < 256; e += 128) zs[e] = z[m0 * LATENT + e];
    __syncthreads();

    {
        int cg = kbase + tid;
        float hw0r[16];
#pragma unroll
        for (int k = 0; k < 16; k++) hw0r[k] = hw0[k * HID + cg];
        float bb = hb0[cg];
#pragma unroll
        for (int r = 0; r < 16; r++) {
            float acc = bb;
#pragma unroll
            for (int k = 0; k < 16; k++) acc = fmaf(zs[r * 16 + k], hw0r[k], acc);
            acc = leaky(acc);
            Ad[tid * H1_AD_STR + r] = pack2(acc, acc);
        }
    }

    u64 acc[2][2];
#pragma unroll
    for (int i = 0; i < 2; i++)
#pragma unroll
        for (int j = 0; j < 2; j++) acc[i][j] = pack2(0.0f, 0.0f);

    float pb[8];
    int pbn = tid & 63, pbk0 = tid >> 6;

    auto ldg_b = [&](int k0) {
#pragma unroll
        for (int r = 0; r < 8; r++)
            pb[r] = hw1[(size_t)(k0 + pbk0 + r * 2) * HID + n0 + pbn];
    };
    auto sts_b = [&](int s) {
#pragma unroll
        for (int r = 0; r < 8; r++) Bs[s][pbk0 + r * 2][pbn] = pb[r];
    };

    ldg_b(kbase);
    sts_b(0);
    __syncthreads();

    int p = 0;
    for (int t = 0; t < 8; t++) {
        if (t + 1 < 8) ldg_b(kbase + (t + 1) * 16);
#pragma unroll
        for (int k = 0; k < 16; k++) {
            int kk = t * 16 + k;
            u64 ra0 = Ad[kk * H1_AD_STR + ty * 2];
            u64 ra1 = Ad[kk * H1_AD_STR + ty * 2 + 1];
            u64 rb0 = *(const u64*)&Bs[p][k][tx * 2];
            u64 rb1 = *(const u64*)&Bs[p][k][tx * 2 + 32];
            fma2(acc[0][0], ra0, rb0); fma2(acc[0][1], ra0, rb1);
            fma2(acc[1][0], ra1, rb0); fma2(acc[1][1], ra1, rb1);
        }
        if (t + 1 < 8) {
            sts_b(p ^ 1);
            __syncthreads();
        }
        p ^= 1;
    }

    float* outp = partial + (size_t)blockIdx.z * (NB * HID);
#pragma unroll
    for (int i = 0; i < 2; i++) {
        int m = m0 + ty * 2 + i;
#pragma unroll
        for (int j = 0; j < 2; j++) {
            float lo, hi;
            asm("mov.b64 {%0, %1}, %2;" : "=f"(lo), "=f"(hi) : "l"(acc[i][j]));
            int n = n0 + tx * 2 + j * 32;
            outp[(size_t)m * HID + n] = lo;
            outp[(size_t)m * HID + n + 1] = hi;
        }
    }
}

// ---------------------------------------------------------------------------
// h1 reduce: sum 4 partials + bias + leaky + fp16 hi/lo split. PDL consumer.
// ---------------------------------------------------------------------------
__global__ void __launch_bounds__(1024)
k_h1red(const float* __restrict__ partial, const float* __restrict__ bias,
        __half* __restrict__ Ch, __half* __restrict__ Cl) {
    int p = blockIdx.x * 1024 + threadIdx.x;
    int m = p >> 8;
    int n = (p & 255) * 2;
    float b0 = bias[n], b1 = bias[n + 1];   // independent input
    gdc_wait();                              // partials ready
    const float* base = partial + (size_t)m * HID + n;
    float2 s0 = *(const float2*)(base);
    float2 s1 = *(const float2*)(base + NB * HID);
    float2 s2 = *(const float2*)(base + 2 * NB * HID);
    float2 s3 = *(const float2*)(base + 3 * NB * HID);
    float v0 = leaky(s0.x + s1.x + s2.x + s3.x + b0);
    float v1 = leaky(s0.y + s1.y + s2.y + s3.y + b1);
    float h0f = __half2float(__float2half_rn(v0));
    float h1f = __half2float(__float2half_rn(v1));
    *(uint32_t*)&Ch[(size_t)m * HID + n] = packh2(h0f, h1f);
    *(uint32_t*)&Cl[(size_t)m * HID + n] = packh2(v0 - h0f, v1 - h1f);
}

// ---------------------------------------------------------------------------
// wb GEMM via fp16 mma (2-split), 132 CTAs x 256 threads, warp m64 x n24,
// double-buffered + ldmatrix; K-tile 64. PDL consumer: prefetches the first
// B tile (hw2, independent) BEFORE griddepcontrol.wait.
// ---------------------------------------------------------------------------
#define KT 64
#define BNW 96
#define ASTR 72
#define BSTR 72
#define STG_H (2 * 128 * ASTR + 2 * BNW * BSTR)   // halves per stage
#define WB_SMEM_BYTES (2 * STG_H * 2)

__global__ void __launch_bounds__(256)
k_wbgemm(const __half* __restrict__ Ah_g, const __half* __restrict__ Al_g,
         const float* __restrict__ Bg, const float* __restrict__ bias,
         float* __restrict__ Cout) {
    extern __shared__ __align__(16) __half smh[];
    uint32_t sb = smem_u32(smh);

    int tid = threadIdx.x;
    int lane = tid & 31;
    int wid = tid >> 5;
    int g4 = lane >> 2;
    int t4 = lane & 3;
    int wm = wid & 1;
    int wn = wid >> 1;
    int n0 = blockIdx.x * BNW;

    int bn = tid % BNW, bkh = tid / BNW;     // B staging: threads < 192
    bool bact = tid < 192;
    bool bok = bact && (n0 + bn) < OUTSZ;
    int brot = (bn >> 3) & 15;

    int rA = (wm * 64 + (lane & 15)) * ASTR + (lane >> 4) * 8;
    int rB01 = (wn * 24 + (lane & 7) + ((lane >> 4) << 3)) * BSTR
             + ((lane >> 3) & 1) * 8;
    int rB2 = (wn * 24 + 16 + (lane & 7)) * BSTR + ((lane >> 3) & 1) * 8;

    float4 acc[4][3];
#pragma unroll
    for (int i = 0; i < 4; i++)
#pragma unroll
        for (int j = 0; j < 3; j++) acc[i][j] = make_float4(0.f, 0.f, 0.f, 0.f);

    u64 pah[8], pal[8];
    float pb[32];

    auto ldg_A = [&](int kt) {
#pragma unroll
        for (int i = 0; i < 8; i++) {
            int idx = tid + i * 256;
            int m = idx >> 4, j = idx & 15;
            pah[i] = *(const u64*)&Ah_g[(size_t)m * HID + kt + j * 4];
            pal[i] = *(const u64*)&Al_g[(size_t)m * HID + kt + j * 4];
        }
    };
    auto ldg_B = [&](int kt) {
        if (bact) {
            const float* bp = Bg + (size_t)(kt + bkh * 32) * OUTSZ + n0 + bn;
#pragma unroll
            for (int j = 0; j < 32; j++)
                pb[j] = bok ? bp[(size_t)j * OUTSZ] : 0.0f;
        }
    };
    auto sts_tile = [&](int s) {
        __half* As_h = smh + s * STG_H;
        __half* As_l = As_h + 128 * ASTR;
        __half* Bs_h = As_l + 128 * ASTR;
        __half* Bs_l = Bs_h + BNW * BSTR;
#pragma unroll
        for (int i = 0; i < 8; i++) {
            int idx = tid + i * 256;
            int m = idx >> 4, j = idx & 15;
            *(u64*)&As_h[m * ASTR + j * 4] = pah[i];
            *(u64*)&As_l[m * ASTR + j * 4] = pal[i];
        }
        if (bact) {
#pragma unroll
            for (int s2 = 0; s2 < 16; s2++) {
                int jr = (s2 + brot) & 15;
                float v0 = pb[2 * jr], v1 = pb[2 * jr + 1];
                float h0 = __half2float(__float2half_rn(v0));
                float h1 = __half2float(__float2half_rn(v1));
                *(uint32_t*)&Bs_h[bn * BSTR + bkh * 32 + 2 * jr] = packh2(h0, h1);
                *(uint32_t*)&Bs_l[bn * BSTR + bkh * 32 + 2 * jr] =
                    packh2(v0 - h0, v1 - h1);
            }
        }
    };

    ldg_B(0);          // independent of h1 — overlaps producer tail
    gdc_wait();        // h1 hi/lo ready
    ldg_A(0);
    sts_tile(0);
    __syncthreads();

    int p = 0;
    for (int t = 0; t < HID / KT; t++) {
        if (t + 1 < HID / KT) { ldg_A((t + 1) * KT); ldg_B((t + 1) * KT); }

        uint32_t bAh = sb + 2 * (p * STG_H);
        uint32_t bAl = bAh + 2 * 128 * ASTR;
        uint32_t bBh = bAl + 2 * 128 * ASTR;
        uint32_t bBl = bBh + 2 * BNW * BSTR;

#pragma unroll
        for (int ks = 0; ks < KT; ks += 16) {
            uint32_t ah[4][4], al[4][4];
#pragma unroll
            for (int mf = 0; mf < 4; mf++) {
                ldsm4(ah[mf], bAh + 2 * (rA + mf * 16 * ASTR + ks));
                ldsm4(al[mf], bAl + 2 * (rA + mf * 16 * ASTR + ks));
            }
            uint32_t b01h[4], b01l[4], b2h[2], b2l[2];
            ldsm4(b01h, bBh + 2 * (rB01 + ks));
            ldsm4(b01l, bBl + 2 * (rB01 + ks));
            ldsm2(b2h, bBh + 2 * (rB2 + ks));
            ldsm2(b2l, bBl + 2 * (rB2 + ks));
#pragma unroll
            for (int mf = 0; mf < 4; mf++) {
                mma_f16(acc[mf][0], ah[mf], b01h);
                mma_f16(acc[mf][0], ah[mf], b01l);
                mma_f16(acc[mf][0], al[mf], b01h);
                mma_f16(acc[mf][1], ah[mf], b01h + 2);
                mma_f16(acc[mf][1], ah[mf], b01l + 2);
                mma_f16(acc[mf][1], al[mf], b01h + 2);
                mma_f16(acc[mf][2], ah[mf], b2h);
                mma_f16(acc[mf][2], ah[mf], b2l);
                mma_f16(acc[mf][2], al[mf], b2h);
            }
        }
        if (t + 1 < HID / KT) {
            sts_tile(p ^ 1);
            __syncthreads();
        }
        p ^= 1;
    }

    // epilogue: bias + permuted scatter
#pragma unroll
    for (int mf = 0; mf < 4; mf++) {
        int m = wm * 64 + mf * 16 + g4;
#pragma unroll
        for (int nf = 0; nf < 3; nf++) {
            int n = n0 + wn * 24 + nf * 8 + t4 * 2;
            if (n < OUTSZ) {
                Cout[(size_t)m * OUTSZ_PAD + perm_wb(n)] = acc[mf][nf].x + bias[n];
                Cout[(size_t)(m + 8) * OUTSZ_PAD + perm_wb(n)] = acc[mf][nf].z + bias[n];
            }
            if (n + 1 < OUTSZ) {
                Cout[(size_t)m * OUTSZ_PAD + perm_wb(n + 1)] = acc[mf][nf].y + bias[n + 1];
                Cout[(size_t)(m + 8) * OUTSZ_PAD + perm_wb(n + 1)] = acc[mf][nf].w + bias[n + 1];
            }
        }
    }
}

// ---------------------------------------------------------------------------
// Decoder via fp16 mma (2-split): 2 CTAs per b (grid 256), 512 threads
// (16 warps: wm 0..3 m16, wn 0..3 n16), 64 g-rows per CTA. 57 KB smem ->
// 2+ CTAs/SM for cross-CTA latency hiding. PDL consumer.
// ---------------------------------------------------------------------------
#define XSH 72
#define WSH 72
#define DXROWS 64
#define XBUFH (DXROWS * XSH)      // 4608 halves
#define WBUFH (DD * WSH)          // 4608 halves
#define DEC_SMEM_BYTES ((4 * XBUFH + 2 * WBUFH) * 2 + 8 * DXROWS * 4)

__global__ void __launch_bounds__(512)
k_decode(const float* __restrict__ logP, float* __restrict__ out) {
    extern __shared__ __align__(16) __half smh[];
    __half* XAh = smh;
    __half* XAl = smh + XBUFH;
    __half* XBh = smh + 2 * XBUFH;
    __half* XBl = smh + 3 * XBUFH;
    __half* Wth = smh + 4 * XBUFH;
    __half* Wtl = smh + 4 * XBUFH + WBUFH;
    float* part = (float*)(smh + 4 * XBUFH + 2 * WBUFH);
    uint32_t sb = smem_u32(smh);
    uint32_t bXA_h = sb, bXA_l = sb + 2 * XBUFH;
    uint32_t bXB_h = sb + 4 * XBUFH, bXB_l = sb + 6 * XBUFH;
    uint32_t bW_h = sb + 8 * XBUFH, bW_l = bW_h + 2 * WBUFH;

    int b = blockIdx.x >> 1;
    int gbase = (blockIdx.x & 1) * DXROWS;
    int tid = threadIdx.x;
    int lane = tid & 31;
    int wid = tid >> 5;
    int g4 = lane >> 2;
    int t4 = lane & 3;
    int wm = wid & 3;          // m16 tile over 64 rows
    int wn = wid >> 2;         // n16 tile, 0..3
    const float* brow = g_wb + (size_t)b * OUTSZ_PAD;

    int rX = (wm * 16 + (lane & 15)) * XSH + (lane >> 4) * 8;
    int rW = (wn * 16 + (lane & 7) + ((lane >> 4) << 3)) * WSH
           + ((lane >> 3) & 1) * 8;

    int wsi = tid & 63;                 // W row i
    int wsj0 = (tid >> 6) * 8;          // 8 consecutive j per thread
    int gl = tid & 63;                  // local g
    int q = tid >> 6;                   // 0..7

    float xin = logP[b * NG + gbase + gl];   // independent input
    gdc_wait();                               // g_wb ready

    // W layer-0 prefetch
    float wv[8];
    {
        float4 wa = *(const float4*)&brow[wsi * DD + wsj0];
        float4 wb4 = *(const float4*)&brow[wsi * DD + wsj0 + 4];
        wv[0] = wa.x; wv[1] = wa.y; wv[2] = wa.z; wv[3] = wa.w;
        wv[4] = wb4.x; wv[5] = wb4.y; wv[6] = wb4.z; wv[7] = wb4.w;
    }

    // ---- first layer: X0 = sin(30*(xin*W0 + b0)), fp16 hi/lo, rotated ----
    {
        int rot = (gl >> 3) & 3;
        float b0v = brow[12608];
#pragma unroll
        for (int s = 0; s < 4; s++) {
            int j = q * 8 + 2 * ((s + rot) & 3);
            float v0 = fsin(30.0f * fmaf(xin, brow[OFF_W0 + j], b0v));
            float v1 = fsin(30.0f * fmaf(xin, brow[OFF_W0 + j + 1], b0v));
            float h0 = __half2float(__float2half_rn(v0));
            float h1 = __half2float(__float2half_rn(v1));
            *(uint32_t*)&XAh[gl * XSH + j] = packh2(h0, h1);
            *(uint32_t*)&XAl[gl * XSH + j] = packh2(v0 - h0, v1 - h1);
        }
    }
    __syncthreads();

#pragma unroll 1
    for (int it = 0; it < 3; it++) {
        // stage W transposed, fp16 hi/lo
#pragma unroll
        for (int jj = 0; jj < 8; jj++) {
            int j = wsj0 + jj;
            float hf = __half2float(__float2half_rn(wv[jj]));
            Wth[j * WSH + wsi] = __float2half_rn(hf);
            Wtl[j * WSH + wsi] = __float2half_rn(wv[jj] - hf);
        }
        float biasE[2], biasO[2];
#pragma unroll
        for (int nf = 0; nf < 2; nf++) {
            int col = wn * 16 + nf * 8 + 2 * t4;
            biasE[nf] = brow[OFF_B + it * DD + col];
            biasO[nf] = brow[OFF_B + it * DD + col + 1];
        }
        __syncthreads();

        // prefetch next layer's W (overlaps MMA below)
        float wvn[8];
        if (it < 2) {
            const float* Wg = brow + (it + 1) * DD * DD;
            float4 wa = *(const float4*)&Wg[wsi * DD + wsj0];
            float4 wb4 = *(const float4*)&Wg[wsi * DD + wsj0 + 4];
            wvn[0] = wa.x; wvn[1] = wa.y; wvn[2] = wa.z; wvn[3] = wa.w;
            wvn[4] = wb4.x; wvn[5] = wb4.y; wvn[6] = wb4.z; wvn[7] = wb4.w;
        }

        uint32_t bXh = (it & 1) ? bXB_h : bXA_h;
        uint32_t bXl = (it & 1) ? bXB_l : bXA_l;
        __half* Xoh = (it & 1) ? XAh : XBh;
        __half* Xol = (it & 1) ? XAl : XBl;

        float4 acc[2];
#pragma unroll
        for (int nf = 0; nf < 2; nf++)
            acc[nf] = make_float4(biasE[nf], biasO[nf], biasE[nf], biasO[nf]);

        int m = wm * 16 + g4;
#pragma unroll
        for (int k16 = 0; k16 < DD; k16 += 16) {
            uint32_t ah[4], al[4], bh[4], bl[4];
            ldsm4(ah, bXh + 2 * (rX + k16));
            ldsm4(al, bXl + 2 * (rX + k16));
            ldsm4(bh, bW_h + 2 * (rW + k16));
            ldsm4(bl, bW_l + 2 * (rW + k16));
            mma_f16(acc[0], ah, bh);
            mma_f16(acc[0], ah, bl);
            mma_f16(acc[0], al, bh);
            mma_f16(acc[1], ah, bh + 2);
            mma_f16(acc[1], ah, bl + 2);
            mma_f16(acc[1], al, bh + 2);
        }

        // sin + split + store (c0,c1 -> row m; c2,c3 -> row m+8)
#pragma unroll
        for (int nf = 0; nf < 2; nf++) {
            int col = wn * 16 + nf * 8 + 2 * t4;
            float4 a = acc[nf];
            float v0 = fsin(a.x), v1 = fsin(a.y);
            float v2 = fsin(a.z), v3 = fsin(a.w);
            float h0 = __half2float(__float2half_rn(v0));
            float h1 = __half2float(__float2half_rn(v1));
            float h2 = __half2float(__float2half_rn(v2));
            float h3 = __half2float(__float2half_rn(v3));
            *(uint32_t*)&Xoh[m * XSH + col] = packh2(h0, h1);
            *(uint32_t*)&Xol[m * XSH + col] = packh2(v0 - h0, v1 - h1);
            *(uint32_t*)&Xoh[(m + 8) * XSH + col] = packh2(h2, h3);
            *(uint32_t*)&Xol[(m + 8) * XSH + col] = packh2(v2 - h2, v3 - h3);
        }
        __syncthreads();
#pragma unroll
        for (int j = 0; j < 8; j++) wv[j] = wvn[j];
    }

    // ---- final layer: out = (X3 . W4) + b4 (X3 in XB after it=2) ----
    {
        float s = 0.0f;
#pragma unroll
        for (int ii = 0; ii < 8; ii++) {
            int i = q * 8 + ii;
            float xv = __half2float(XBh[gl * XSH + i]) + __half2float(XBl[gl * XSH + i]);
            s = fmaf(xv, brow[OFF_W4 + i], s);
        }
        part[q * DXROWS + gl] = s;
    }
    __syncthreads();
    if (tid < DXROWS) {
        float acc = brow[12609];
#pragma unroll
        for (int qq = 0; qq < 8; qq++) acc += part[qq * DXROWS + tid];
        out[b * NG + gbase + tid] = fmaf(acc, 500.0f, 1500.0f);
    }
}

// ---------------------------------------------------------------------------
extern "C" void kernel_launch(void* const* d_in, const int* in_sizes, int n_in,
                              void* d_out, int out_size) {
    (void)in_sizes; (void)n_in; (void)out_size;
    const float* z    = (const float*)d_in[0];
    const float* logP = (const float*)d_in[1];
    const float* hw0  = (const float*)d_in[2];
    const float* hb0  = (const float*)d_in[3];
    const float* hw1  = (const float*)d_in[4];
    const float* hb1  = (const float*)d_in[5];
    const float* hw2  = (const float*)d_in[6];
    const float* hb2  = (const float*)d_in[7];
    float* out = (float*)d_out;

    float *p_wb, *p_h1p;
    __half *p_h1h, *p_h1l;
    cudaGetSymbolAddress((void**)&p_h1p, g_h1p);
    cudaGetSymbolAddress((void**)&p_h1h, g_h1h);
    cudaGetSymbolAddress((void**)&p_h1l, g_h1l);
    cudaGetSymbolAddress((void**)&p_wb, g_wb);

    cudaFuncSetAttribute(k_wbgemm, cudaFuncAttributeMaxDynamicSharedMemorySize,
                         WB_SMEM_BYTES);
    cudaFuncSetAttribute(k_decode, cudaFuncAttributeMaxDynamicSharedMemorySize,
                         DEC_SMEM_BYTES);

    cudaLaunchAttribute pdl[1];
    pdl[0].id = cudaLaunchAttributeProgrammaticStreamSerialization;
    pdl[0].val.programmaticStreamSerializationAllowed = 1;

    // 1) h1 split-K partials (fused h0 per chunk): 256 CTAs
    {
        dim3 grid(HID / 64, NB / 16, 4);
        k_h1split<<<grid, 128>>>(z, hw0, hb0, hw1, p_h1p);
    }

    // 2) h1 reduce (PDL)
    {
        cudaLaunchConfig_t cfg = {};
        cfg.gridDim = dim3(32, 1, 1);
        cfg.blockDim = dim3(1024, 1, 1);
        cfg.attrs = pdl;
        cfg.numAttrs = 1;
        cudaLaunchKernelEx(&cfg, k_h1red, (const float*)p_h1p,
                           (const float*)hb1, p_h1h, p_h1l);
    }

    // 3) wb GEMM (PDL: B prefetch before wait)
    {
        cudaLaunchConfig_t cfg = {};
        cfg.gridDim = dim3((OUTSZ + BNW - 1) / BNW, 1, 1);
        cfg.blockDim = dim3(256, 1, 1);
        cfg.dynamicSmemBytes = WB_SMEM_BYTES;
        cfg.attrs = pdl;
        cfg.numAttrs = 1;
        cudaLaunchKernelEx(&cfg, k_wbgemm, (const __half*)p_h1h,
                           (const __half*)p_h1l, (const float*)hw2,
                           (const float*)hb2, p_wb);
    }

    // 4) decoder (PDL), 2 CTAs per b
    {
        cudaLaunchConfig_t cfg = {};
        cfg.gridDim = dim3(2 * NB, 1, 1);
        cfg.blockDim = dim3(512, 1, 1);
        cfg.dynamicSmemBytes = DEC_SMEM_BYTES;
        cfg.attrs = pdl;
        cfg.numAttrs = 1;
        cudaLaunchKernelEx(&cfg, k_decode, (const float*)logP, out);
    }
}